// round 13
// baseline (speedup 1.0000x reference)
#include <cuda_runtime.h>
#include <cuda_fp16.h>
#include <cstdint>
#include <cstddef>

// ---------------------------------------------------------------------------
// Fused GRU cell, fp16 tensor-core path (compute_103-safe PTX).
// R13: single-launch fp32->fp16 conversion (grid.y segments), GEMM = R12
// (BK=128, 2-stage, 8 barriers, 2 CTAs/SM) with the next-stage fill moved to
// ks2..5 so the post-barrier LDSM->MMA restart isn't polluted by cp.asyncs.
//
// B operand rows (96), per wn slice s = wn*48:
//   rows [s+ 0,s+16): W_gate[n0+wn*16+u]     -> r (nb 0,1)
//   rows [s+16,s+32): W_gate[512+n0+wn*16+u] -> z (nb 2,3)
//   rows [s+32,s+48): Wi/Wh[n0+wn*16+u]      -> i/h (nb 4,5, phase split)
// kt<4: X=input, ih=Wi -> alo. kt>=4: X=hidden, ih=Wh -> ahi.
// Epilogue uses ORIGINAL fp32 hidden for the z*h term.
// ---------------------------------------------------------------------------

// ---- fp16 scratch (device global: allocation-free) ----
static constexpr size_t OFF_IN  = 0;                        // 16384x512
static constexpr size_t OFF_HID = 8388608;                  // 16384x512
static constexpr size_t OFF_WG  = 16777216;                 // 1024x1024
static constexpr size_t OFF_WI  = 17825792;                 // 512x512
static constexpr size_t OFF_WH  = 18087936;                 // 512x512
static constexpr size_t CVT_TOTAL = 18350080;               // 35MB
__device__ __half g_cvt[CVT_TOTAL];

static constexpr int N4_X  = 2097152;                       // input/hidden f4 count
static constexpr int N4_WG = 262144, N4_WI = 65536, N4_WH = 65536;
static constexpr int N4_W_TOTAL = N4_WG + N4_WI + N4_WH;    // 393216
static constexpr int CVT_BLOCKS = (N4_X + 255) / 256;       // 8192

// grid.y: 0 = input, 1 = hidden, 2 = weights (fused; excess blocks exit)
__global__ void cvt_all_kernel(const float4* __restrict__ input,
                               const float4* __restrict__ hidden,
                               const float4* __restrict__ Wg,
                               const float4* __restrict__ Wi,
                               const float4* __restrict__ Wh) {
    const int i = blockIdx.x * blockDim.x + threadIdx.x;
    const int seg = blockIdx.y;
    const float4* src;
    size_t dst_off;
    int j = i;
    if (seg == 0) {
        src = input;  dst_off = OFF_IN;
    } else if (seg == 1) {
        src = hidden; dst_off = OFF_HID;
    } else {
        if (j >= N4_W_TOTAL) return;
        if (j < N4_WG)                 { src = Wg; dst_off = OFF_WG; }
        else if ((j -= N4_WG) < N4_WI) { src = Wi; dst_off = OFF_WI; }
        else { j -= N4_WI;               src = Wh; dst_off = OFF_WH; }
    }
    const float4 v = src[j];
    __half2* dst = reinterpret_cast<__half2*>(g_cvt + dst_off);
    dst[2 * j]     = __floats2half2_rn(v.x, v.y);
    dst[2 * j + 1] = __floats2half2_rn(v.z, v.w);
}

// ---- helpers ----
__device__ __forceinline__ uint32_t smem_u32(const void* p) {
    uint32_t a;
    asm("{ .reg .u64 t; cvta.to.shared.u64 t, %1; cvt.u32.u64 %0, t; }"
        : "=r"(a) : "l"(p));
    return a;
}

__device__ __forceinline__ void cp16(uint32_t dst, const __half* src) {
    asm volatile("cp.async.cg.shared.global [%0], [%1], 16;"
                 :: "r"(dst), "l"(src) : "memory");
}
#define CP_COMMIT() asm volatile("cp.async.commit_group;" ::: "memory")
#define CP_WAIT0()  asm volatile("cp.async.wait_group 0;" ::: "memory")

__device__ __forceinline__ void ldsm4(uint32_t& r0, uint32_t& r1,
                                      uint32_t& r2, uint32_t& r3, uint32_t addr) {
    asm volatile("ldmatrix.sync.aligned.m8n8.x4.shared.b16 {%0,%1,%2,%3}, [%4];"
                 : "=r"(r0), "=r"(r1), "=r"(r2), "=r"(r3) : "r"(addr));
}

__device__ __forceinline__ void mma16(float* c, const uint32_t* a,
                                      uint32_t b0, uint32_t b1) {
    asm volatile(
        "mma.sync.aligned.m16n8k16.row.col.f32.f16.f16.f32 "
        "{%0,%1,%2,%3}, {%4,%5,%6,%7}, {%8,%9}, {%0,%1,%2,%3};"
        : "+f"(c[0]), "+f"(c[1]), "+f"(c[2]), "+f"(c[3])
        : "r"(a[0]), "r"(a[1]), "r"(a[2]), "r"(a[3]), "r"(b0), "r"(b1));
}

__device__ __forceinline__ float fsigmoid(float x) {
    return 1.0f / (1.0f + __expf(-x));
}
__device__ __forceinline__ float ftanh(float x) {
    float e = __expf(2.0f * x);          // overflow->inf, underflow->0: safe
    return 1.0f - 2.0f / (e + 1.0f);
}

// ---- geometry ----
// Rows are 256B (128 fp16). Physical offset of (row, col byte c):
//   row*256 + (c>>7)*128 + ((c&127) ^ ((row&7)<<4))   [SW128 per 128B half]
static constexpr int A_BYTES     = 128 * 256;          // 32KB
static constexpr int B_BYTES     = 96 * 256;           // 24KB
static constexpr int STAGE_BYTES = A_BYTES + B_BYTES;  // 57344
static constexpr int SMEM_BYTES  = 128 + 2 * STAGE_BYTES;  // 114816/CTA

__device__ __forceinline__ uint32_t fill_off(int u) {
    const int r = u >> 4, cu = u & 15;
    return (uint32_t)(r * 256 + ((cu >> 3) << 7) + (((cu & 7) * 16) ^ ((r & 7) << 4)));
}

// Compute one BK=128 tile (8 x k16); optionally interleave next-stage fill.
// Fill schedule: A 4+4 at ks2,3; B 3+3 at ks4,5; commit ks5. Keeps the
// post-barrier ks0/ks1 window free for the critical LDSM->MMA restart while
// leaving ~2.5 ks (>L2 latency) before the next tile's wait_group 0.
template <bool PH, bool FILL>
__device__ __forceinline__ void compute_tile(
    uint32_t stg, uint32_t fstg, uint32_t aoff0, uint32_t boff0,
    uint32_t fA0, uint32_t fB0,
    const __half*& pA0, const __half* (&pB)[6],
    float (&alo)[2][6][4], float (&ahi)[2][2][4])
{
    uint32_t a[2][2][4];   // A double buffer [buf][mi][reg]
    uint32_t b[6][2];      // B single buffer

    #pragma unroll
    for (int mi = 0; mi < 2; mi++)
        ldsm4(a[0][mi][0], a[0][mi][1], a[0][mi][2], a[0][mi][3],
              stg + aoff0 + mi * 4096);
    #pragma unroll
    for (int p = 0; p < 3; p++)
        ldsm4(b[2 * p][0], b[2 * p][1], b[2 * p + 1][0], b[2 * p + 1][1],
              stg + boff0 + p * 4096);

    #pragma unroll
    for (int ks = 0; ks < 8; ks++) {
        const int cur = ks & 1, nxt = cur ^ 1;
        if (ks < 7) {
            const uint32_t kx = (uint32_t)((ks + 1) << 5);
            #pragma unroll
            for (int mi = 0; mi < 2; mi++)
                ldsm4(a[nxt][mi][0], a[nxt][mi][1], a[nxt][mi][2], a[nxt][mi][3],
                      stg + (aoff0 ^ kx) + mi * 4096);
        }
        if (FILL) {
            if (ks == 2 || ks == 3) {        // A: 4 chunks each
                const int j0 = 4 * (ks - 2);
                #pragma unroll
                for (int j = 0; j < 4; j++)
                    cp16(fstg + fA0 + (uint32_t)(j0 + j) * 4096u,
                         pA0 + (j0 + j) * 8192);
            } else if (ks == 4 || ks == 5) { // B: 3 chunks each
                const int i0 = 3 * (ks - 4);
                #pragma unroll
                for (int i = 0; i < 3; i++)
                    cp16(fstg + fB0 + (uint32_t)(i0 + i) * 4096u, pB[i0 + i]);
                if (ks == 5) CP_COMMIT();
            }
        }
        #pragma unroll
        for (int mi = 0; mi < 2; mi++) {
            #pragma unroll
            for (int nb = 0; nb < 6; nb++) {
                if (PH && nb >= 4)
                    mma16(ahi[mi][nb - 4], a[cur][mi], b[nb][0], b[nb][1]);
                else
                    mma16(alo[mi][nb], a[cur][mi], b[nb][0], b[nb][1]);
            }
        }
        if (ks < 7) {
            const uint32_t kx = (uint32_t)((ks + 1) << 5);
            #pragma unroll
            for (int p = 0; p < 3; p++)
                ldsm4(b[2 * p][0], b[2 * p][1], b[2 * p + 1][0], b[2 * p + 1][1],
                      stg + (boff0 ^ kx) + p * 4096);
        }
    }
    if (FILL) {
        pA0 += 128;
        #pragma unroll
        for (int i = 0; i < 6; i++) pB[i] += 128;
    }
}

__global__ void __launch_bounds__(256, 2)
gru_mma_kernel(const float* __restrict__ hidden,
               const float* __restrict__ bg, const float* __restrict__ bi,
               const float* __restrict__ bh, float* __restrict__ out)
{
    extern __shared__ char dsm[];
    const int tid  = threadIdx.x;
    const int lane = tid & 31;
    const int wid  = tid >> 5;
    const int wm   = wid >> 1;          // 0..3 (M, 32 rows each)
    const int wn   = wid & 1;           // 0..1 (N slice, 16 units each)
    const int n0 = blockIdx.x * 32;     // hidden-unit slice
    const int m0 = blockIdx.y * 128;    // batch-row slice

    const __half* cIn  = g_cvt + OFF_IN;
    const __half* cHid = g_cvt + OFF_HID;
    const __half* cWg  = g_cvt + OFF_WG;
    const __half* cWi  = g_cvt + OFF_WI;
    const __half* cWh  = g_cvt + OFF_WH;

    const uint32_t raw = smem_u32(dsm);
    const uint32_t sb  = (raw + 127u) & ~127u;
    const uint32_t stage0 = sb;
    const uint32_t stage1 = stage0 + STAGE_BYTES;

    // ---- fill state (16B chunk = 8 halfs; 16 chunks per 256B row) ----
    const uint32_t fA0 = fill_off(tid);                        // + j*4096
    const uint32_t fB0 = (uint32_t)A_BYTES + fill_off(tid);    // + i*4096
    const int frow = tid >> 4, fcu = (tid & 15) * 8;
    const __half* pA0 = cIn + (m0 + frow) * 512 + fcu;         // + j*8192 halfs
    const __half* pB[6];
    bool isw[6];
    #pragma unroll
    for (int i = 0; i < 6; i++) {
        const int r = frow + 16 * i;        // 0..95
        const int ws = (r >= 48) ? 1 : 0, rr = r - ws * 48;
        const int un = n0 + ws * 16;
        isw[i] = (rr >= 32);
        if (rr < 16)       pB[i] = cWg + (un + rr) * 1024 + fcu;
        else if (rr < 32)  pB[i] = cWg + (512 + un + rr - 16) * 1024 + fcu;
        else               pB[i] = cWi + (un + rr - 32) * 512 + fcu;
    }
    // Phase switch (after 4 fills of +128): xa = in+row*512+512 -> hid+row*512.
    const ptrdiff_t dxa = (cHid - cIn) - 512;
    const ptrdiff_t dwh = (cWh - cWi) - 512;

    // ---- LDSM base offsets ----
    uint32_t aoff0, boff0;
    {
        const uint32_t arow = (uint32_t)(wm * 32 + (lane & 7) + ((lane >> 3) & 1) * 8);
        const uint32_t acb  = (uint32_t)((lane >> 4) * 16);
        const uint32_t brow = (uint32_t)(wn * 48 + ((lane >> 4) * 8) + (lane & 7));
        const uint32_t bcb  = (uint32_t)(((lane >> 3) & 1) * 16);
        aoff0 = arow * 256 + (acb ^ ((arow & 7) << 4));                     // + mi*4096
        boff0 = (uint32_t)A_BYTES + brow * 256 + (bcb ^ ((brow & 7) << 4)); // + p*4096
    }

    float alo[2][6][4];
    float ahi[2][2][4];
    #pragma unroll
    for (int mi = 0; mi < 2; mi++) {
        #pragma unroll
        for (int nb = 0; nb < 6; nb++)
            #pragma unroll
            for (int e = 0; e < 4; e++) alo[mi][nb][e] = 0.0f;
        #pragma unroll
        for (int nb = 0; nb < 2; nb++)
            #pragma unroll
            for (int e = 0; e < 4; e++) ahi[mi][nb][e] = 0.0f;
    }

    // prologue: fill stage0 for kt=0
    {
        #pragma unroll
        for (int j = 0; j < 8; j++)
            cp16(stage0 + fA0 + (uint32_t)j * 4096u, pA0 + j * 8192);
        pA0 += 128;
        #pragma unroll
        for (int i = 0; i < 6; i++) {
            cp16(stage0 + fB0 + (uint32_t)i * 4096u, pB[i]);
            pB[i] += 128;
        }
        CP_COMMIT();
    }

    // Phase 0: kt = 0..3 (X=input, ih=Wi -> alo)
    #pragma unroll 2
    for (int kt = 0; kt < 4; kt++) {
        const uint32_t stg  = (kt & 1) ? stage1 : stage0;
        const uint32_t fstg = (kt & 1) ? stage0 : stage1;
        CP_WAIT0();
        __syncthreads();
        if (kt == 3) {   // next fill f=4: switch xa->hidden, Wi->Wh
            pA0 += dxa;
            #pragma unroll
            for (int i = 0; i < 6; i++) if (isw[i]) pB[i] += dwh;
        }
        compute_tile<false, true>(stg, fstg, aoff0, boff0, fA0, fB0,
                                  pA0, pB, alo, ahi);
    }
    // Phase 1: kt = 4..7 (X=hidden, ih=Wh -> ahi); last iter fills nothing.
    #pragma unroll 2
    for (int kt = 4; kt < 7; kt++) {
        const uint32_t stg  = (kt & 1) ? stage1 : stage0;
        const uint32_t fstg = (kt & 1) ? stage0 : stage1;
        CP_WAIT0();
        __syncthreads();
        compute_tile<true, true>(stg, fstg, aoff0, boff0, fA0, fB0,
                                 pA0, pB, alo, ahi);
    }
    {
        CP_WAIT0();
        __syncthreads();
        compute_tile<true, false>(stage1, stage0, aoff0, boff0, fA0, fB0,
                                  pA0, pB, alo, ahi);
    }

    // ---- register-resident epilogue (biases from global, fp32 hidden) ----
    #pragma unroll
    for (int mi = 0; mi < 2; mi++) {
        #pragma unroll
        for (int unb = 0; unb < 2; unb++) {
            const int ug = n0 + wn * 16 + unb * 8 + 2 * (lane & 3);  // global unit
            const float br0 = __ldg(&bg[ug]),        br1 = __ldg(&bg[ug + 1]);
            const float bz0 = __ldg(&bg[512 + ug]),  bz1 = __ldg(&bg[512 + ug + 1]);
            const float bi0 = __ldg(&bi[ug]),        bi1 = __ldg(&bi[ug + 1]);
            const float bh0 = __ldg(&bh[ug]),        bh1 = __ldg(&bh[ug + 1]);
            #pragma unroll
            for (int half = 0; half < 2; half++) {
                const int m = wm * 32 + mi * 16 + (lane >> 2) + 8 * half;
                const float rv0 = fsigmoid(alo[mi][0 + unb][2 * half]     + br0);
                const float rv1 = fsigmoid(alo[mi][0 + unb][2 * half + 1] + br1);
                const float zv0 = fsigmoid(alo[mi][2 + unb][2 * half]     + bz0);
                const float zv1 = fsigmoid(alo[mi][2 + unb][2 * half + 1] + bz1);
                const float iv0 = alo[mi][4 + unb][2 * half];
                const float iv1 = alo[mi][4 + unb][2 * half + 1];
                const float hv0 = ahi[mi][unb][2 * half];
                const float hv1 = ahi[mi][unb][2 * half + 1];
                const float2 hg = *(const float2*)&hidden[(m0 + m) * 512 + ug];
                const float ng0 = ftanh(iv0 + bi0 + rv0 * (hv0 + bh0));
                const float ng1 = ftanh(iv1 + bi1 + rv1 * (hv1 + bh1));
                float2 o;
                o.x = (1.0f - zv0) * ng0 + zv0 * hg.x;
                o.y = (1.0f - zv1) * ng1 + zv1 * hg.y;
                *(float2*)&out[(m0 + m) * 512 + ug] = o;
            }
        }
    }
}

extern "C" void kernel_launch(void* const* d_in, const int* in_sizes, int n_in,
                              void* d_out, int out_size)
{
    const float* input  = (const float*)d_in[0];
    const float* hidden = (const float*)d_in[1];
    const float* Wg     = (const float*)d_in[2];
    const float* bg     = (const float*)d_in[3];
    const float* Wi     = (const float*)d_in[4];
    const float* bi     = (const float*)d_in[5];
    const float* Wh     = (const float*)d_in[6];
    const float* bh     = (const float*)d_in[7];
    float* out = (float*)d_out;

    // single fused fp32 -> fp16 conversion pass (grid.y segments)
    cvt_all_kernel<<<dim3(CVT_BLOCKS, 3), 256>>>(
        (const float4*)input, (const float4*)hidden,
        (const float4*)Wg, (const float4*)Wi, (const float4*)Wh);

    cudaFuncSetAttribute(gru_mma_kernel,
                         cudaFuncAttributeMaxDynamicSharedMemorySize, SMEM_BYTES);
    // grid.x = 16 n-slices of 32 units, grid.y = 128 batch tiles of 128 rows
    gru_mma_kernel<<<dim3(16, 128), 256, SMEM_BYTES>>>(hidden, bg, bi, bh, out);
}

// round 14
// speedup vs baseline: 1.0114x; 1.0114x over previous
#include <cuda_runtime.h>
#include <cuda_fp16.h>
#include <cstdint>
#include <cstddef>

// ---------------------------------------------------------------------------
// Fused GRU cell, fp16 tensor-core path (compute_103-safe PTX).
// R14: recombination of measured-best components — R12's GEMM (BK=128,
// 2-stage, 8 barriers, 2 CTAs/SM, fill A@ks0 + B@ks1 with early commit,
// measured 133.9us) + R13's single-launch fp32->fp16 conversion (grid.y
// segments, measured ~17us including launch gap).
//
// B operand rows (96), per wn slice s = wn*48:
//   rows [s+ 0,s+16): W_gate[n0+wn*16+u]     -> r (nb 0,1)
//   rows [s+16,s+32): W_gate[512+n0+wn*16+u] -> z (nb 2,3)
//   rows [s+32,s+48): Wi/Wh[n0+wn*16+u]      -> i/h (nb 4,5, phase split)
// kt<4: X=input, ih=Wi -> alo. kt>=4: X=hidden, ih=Wh -> ahi.
// Epilogue uses ORIGINAL fp32 hidden for the z*h term.
// ---------------------------------------------------------------------------

// ---- fp16 scratch (device global: allocation-free) ----
static constexpr size_t OFF_IN  = 0;                        // 16384x512
static constexpr size_t OFF_HID = 8388608;                  // 16384x512
static constexpr size_t OFF_WG  = 16777216;                 // 1024x1024
static constexpr size_t OFF_WI  = 17825792;                 // 512x512
static constexpr size_t OFF_WH  = 18087936;                 // 512x512
static constexpr size_t CVT_TOTAL = 18350080;               // 35MB
__device__ __half g_cvt[CVT_TOTAL];

static constexpr int N4_X  = 2097152;                       // input/hidden f4 count
static constexpr int N4_WG = 262144, N4_WI = 65536, N4_WH = 65536;
static constexpr int N4_W_TOTAL = N4_WG + N4_WI + N4_WH;    // 393216
static constexpr int CVT_BLOCKS = (N4_X + 255) / 256;       // 8192

// grid.y: 0 = input, 1 = hidden, 2 = weights (fused; excess blocks exit)
__global__ void cvt_all_kernel(const float4* __restrict__ input,
                               const float4* __restrict__ hidden,
                               const float4* __restrict__ Wg,
                               const float4* __restrict__ Wi,
                               const float4* __restrict__ Wh) {
    const int i = blockIdx.x * blockDim.x + threadIdx.x;
    const int seg = blockIdx.y;
    const float4* src;
    size_t dst_off;
    int j = i;
    if (seg == 0) {
        src = input;  dst_off = OFF_IN;
    } else if (seg == 1) {
        src = hidden; dst_off = OFF_HID;
    } else {
        if (j >= N4_W_TOTAL) return;
        if (j < N4_WG)                 { src = Wg; dst_off = OFF_WG; }
        else if ((j -= N4_WG) < N4_WI) { src = Wi; dst_off = OFF_WI; }
        else { j -= N4_WI;               src = Wh; dst_off = OFF_WH; }
    }
    const float4 v = src[j];
    __half2* dst = reinterpret_cast<__half2*>(g_cvt + dst_off);
    dst[2 * j]     = __floats2half2_rn(v.x, v.y);
    dst[2 * j + 1] = __floats2half2_rn(v.z, v.w);
}

// ---- helpers ----
__device__ __forceinline__ uint32_t smem_u32(const void* p) {
    uint32_t a;
    asm("{ .reg .u64 t; cvta.to.shared.u64 t, %1; cvt.u32.u64 %0, t; }"
        : "=r"(a) : "l"(p));
    return a;
}

__device__ __forceinline__ void cp16(uint32_t dst, const __half* src) {
    asm volatile("cp.async.cg.shared.global [%0], [%1], 16;"
                 :: "r"(dst), "l"(src) : "memory");
}
#define CP_COMMIT() asm volatile("cp.async.commit_group;" ::: "memory")
#define CP_WAIT0()  asm volatile("cp.async.wait_group 0;" ::: "memory")

__device__ __forceinline__ void ldsm4(uint32_t& r0, uint32_t& r1,
                                      uint32_t& r2, uint32_t& r3, uint32_t addr) {
    asm volatile("ldmatrix.sync.aligned.m8n8.x4.shared.b16 {%0,%1,%2,%3}, [%4];"
                 : "=r"(r0), "=r"(r1), "=r"(r2), "=r"(r3) : "r"(addr));
}

__device__ __forceinline__ void mma16(float* c, const uint32_t* a,
                                      uint32_t b0, uint32_t b1) {
    asm volatile(
        "mma.sync.aligned.m16n8k16.row.col.f32.f16.f16.f32 "
        "{%0,%1,%2,%3}, {%4,%5,%6,%7}, {%8,%9}, {%0,%1,%2,%3};"
        : "+f"(c[0]), "+f"(c[1]), "+f"(c[2]), "+f"(c[3])
        : "r"(a[0]), "r"(a[1]), "r"(a[2]), "r"(a[3]), "r"(b0), "r"(b1));
}

__device__ __forceinline__ float fsigmoid(float x) {
    return 1.0f / (1.0f + __expf(-x));
}
__device__ __forceinline__ float ftanh(float x) {
    float e = __expf(2.0f * x);          // overflow->inf, underflow->0: safe
    return 1.0f - 2.0f / (e + 1.0f);
}

// ---- geometry ----
// Rows are 256B (128 fp16). Physical offset of (row, col byte c):
//   row*256 + (c>>7)*128 + ((c&127) ^ ((row&7)<<4))   [SW128 per 128B half]
static constexpr int A_BYTES     = 128 * 256;          // 32KB
static constexpr int B_BYTES     = 96 * 256;           // 24KB
static constexpr int STAGE_BYTES = A_BYTES + B_BYTES;  // 57344
static constexpr int SMEM_BYTES  = 128 + 2 * STAGE_BYTES;  // 114816/CTA

__device__ __forceinline__ uint32_t fill_off(int u) {
    const int r = u >> 4, cu = u & 15;
    return (uint32_t)(r * 256 + ((cu >> 3) << 7) + (((cu & 7) * 16) ^ ((r & 7) << 4)));
}

// Compute one BK=128 tile (8 x k16); optionally interleave next-stage fill.
// Fill schedule (R12, measured best): A's 8 chunks at ks0, B's 6 chunks at
// ks1, COMMIT at ks1 — early LSU issue smooths traffic and leaves ~6.5 ks
// of completion window before the next tile's wait_group 0.
template <bool PH, bool FILL>
__device__ __forceinline__ void compute_tile(
    uint32_t stg, uint32_t fstg, uint32_t aoff0, uint32_t boff0,
    uint32_t fA0, uint32_t fB0,
    const __half*& pA0, const __half* (&pB)[6],
    float (&alo)[2][6][4], float (&ahi)[2][2][4])
{
    uint32_t a[2][2][4];   // A double buffer [buf][mi][reg]
    uint32_t b[6][2];      // B single buffer

    #pragma unroll
    for (int mi = 0; mi < 2; mi++)
        ldsm4(a[0][mi][0], a[0][mi][1], a[0][mi][2], a[0][mi][3],
              stg + aoff0 + mi * 4096);
    #pragma unroll
    for (int p = 0; p < 3; p++)
        ldsm4(b[2 * p][0], b[2 * p][1], b[2 * p + 1][0], b[2 * p + 1][1],
              stg + boff0 + p * 4096);

    #pragma unroll
    for (int ks = 0; ks < 8; ks++) {
        const int cur = ks & 1, nxt = cur ^ 1;
        if (ks < 7) {
            const uint32_t kx = (uint32_t)((ks + 1) << 5);
            #pragma unroll
            for (int mi = 0; mi < 2; mi++)
                ldsm4(a[nxt][mi][0], a[nxt][mi][1], a[nxt][mi][2], a[nxt][mi][3],
                      stg + (aoff0 ^ kx) + mi * 4096);
        }
        if (FILL) {
            if (ks == 0) {             // A: all 8 chunks
                #pragma unroll
                for (int j = 0; j < 8; j++)
                    cp16(fstg + fA0 + (uint32_t)j * 4096u, pA0 + j * 8192);
            } else if (ks == 1) {      // B: all 6 chunks + early commit
                #pragma unroll
                for (int i = 0; i < 6; i++)
                    cp16(fstg + fB0 + (uint32_t)i * 4096u, pB[i]);
                CP_COMMIT();
            }
        }
        #pragma unroll
        for (int mi = 0; mi < 2; mi++) {
            #pragma unroll
            for (int nb = 0; nb < 6; nb++) {
                if (PH && nb >= 4)
                    mma16(ahi[mi][nb - 4], a[cur][mi], b[nb][0], b[nb][1]);
                else
                    mma16(alo[mi][nb], a[cur][mi], b[nb][0], b[nb][1]);
            }
        }
        if (ks < 7) {
            const uint32_t kx = (uint32_t)((ks + 1) << 5);
            #pragma unroll
            for (int p = 0; p < 3; p++)
                ldsm4(b[2 * p][0], b[2 * p][1], b[2 * p + 1][0], b[2 * p + 1][1],
                      stg + (boff0 ^ kx) + p * 4096);
        }
    }
    if (FILL) {
        pA0 += 128;
        #pragma unroll
        for (int i = 0; i < 6; i++) pB[i] += 128;
    }
}

__global__ void __launch_bounds__(256, 2)
gru_mma_kernel(const float* __restrict__ hidden,
               const float* __restrict__ bg, const float* __restrict__ bi,
               const float* __restrict__ bh, float* __restrict__ out)
{
    extern __shared__ char dsm[];
    const int tid  = threadIdx.x;
    const int lane = tid & 31;
    const int wid  = tid >> 5;
    const int wm   = wid >> 1;          // 0..3 (M, 32 rows each)
    const int wn   = wid & 1;           // 0..1 (N slice, 16 units each)
    const int n0 = blockIdx.x * 32;     // hidden-unit slice
    const int m0 = blockIdx.y * 128;    // batch-row slice

    const __half* cIn  = g_cvt + OFF_IN;
    const __half* cHid = g_cvt + OFF_HID;
    const __half* cWg  = g_cvt + OFF_WG;
    const __half* cWi  = g_cvt + OFF_WI;
    const __half* cWh  = g_cvt + OFF_WH;

    const uint32_t raw = smem_u32(dsm);
    const uint32_t sb  = (raw + 127u) & ~127u;
    const uint32_t stage0 = sb;
    const uint32_t stage1 = stage0 + STAGE_BYTES;

    // ---- fill state (16B chunk = 8 halfs; 16 chunks per 256B row) ----
    const uint32_t fA0 = fill_off(tid);                        // + j*4096
    const uint32_t fB0 = (uint32_t)A_BYTES + fill_off(tid);    // + i*4096
    const int frow = tid >> 4, fcu = (tid & 15) * 8;
    const __half* pA0 = cIn + (m0 + frow) * 512 + fcu;         // + j*8192 halfs
    const __half* pB[6];
    bool isw[6];
    #pragma unroll
    for (int i = 0; i < 6; i++) {
        const int r = frow + 16 * i;        // 0..95
        const int ws = (r >= 48) ? 1 : 0, rr = r - ws * 48;
        const int un = n0 + ws * 16;
        isw[i] = (rr >= 32);
        if (rr < 16)       pB[i] = cWg + (un + rr) * 1024 + fcu;
        else if (rr < 32)  pB[i] = cWg + (512 + un + rr - 16) * 1024 + fcu;
        else               pB[i] = cWi + (un + rr - 32) * 512 + fcu;
    }
    // Phase switch (after 4 fills of +128): xa = in+row*512+512 -> hid+row*512.
    const ptrdiff_t dxa = (cHid - cIn) - 512;
    const ptrdiff_t dwh = (cWh - cWi) - 512;

    // ---- LDSM base offsets ----
    uint32_t aoff0, boff0;
    {
        const uint32_t arow = (uint32_t)(wm * 32 + (lane & 7) + ((lane >> 3) & 1) * 8);
        const uint32_t acb  = (uint32_t)((lane >> 4) * 16);
        const uint32_t brow = (uint32_t)(wn * 48 + ((lane >> 4) * 8) + (lane & 7));
        const uint32_t bcb  = (uint32_t)(((lane >> 3) & 1) * 16);
        aoff0 = arow * 256 + (acb ^ ((arow & 7) << 4));                     // + mi*4096
        boff0 = (uint32_t)A_BYTES + brow * 256 + (bcb ^ ((brow & 7) << 4)); // + p*4096
    }

    float alo[2][6][4];
    float ahi[2][2][4];
    #pragma unroll
    for (int mi = 0; mi < 2; mi++) {
        #pragma unroll
        for (int nb = 0; nb < 6; nb++)
            #pragma unroll
            for (int e = 0; e < 4; e++) alo[mi][nb][e] = 0.0f;
        #pragma unroll
        for (int nb = 0; nb < 2; nb++)
            #pragma unroll
            for (int e = 0; e < 4; e++) ahi[mi][nb][e] = 0.0f;
    }

    // prologue: fill stage0 for kt=0
    {
        #pragma unroll
        for (int j = 0; j < 8; j++)
            cp16(stage0 + fA0 + (uint32_t)j * 4096u, pA0 + j * 8192);
        pA0 += 128;
        #pragma unroll
        for (int i = 0; i < 6; i++) {
            cp16(stage0 + fB0 + (uint32_t)i * 4096u, pB[i]);
            pB[i] += 128;
        }
        CP_COMMIT();
    }

    // Phase 0: kt = 0..3 (X=input, ih=Wi -> alo)
    #pragma unroll 2
    for (int kt = 0; kt < 4; kt++) {
        const uint32_t stg  = (kt & 1) ? stage1 : stage0;
        const uint32_t fstg = (kt & 1) ? stage0 : stage1;
        CP_WAIT0();
        __syncthreads();
        if (kt == 3) {   // next fill f=4: switch xa->hidden, Wi->Wh
            pA0 += dxa;
            #pragma unroll
            for (int i = 0; i < 6; i++) if (isw[i]) pB[i] += dwh;
        }
        compute_tile<false, true>(stg, fstg, aoff0, boff0, fA0, fB0,
                                  pA0, pB, alo, ahi);
    }
    // Phase 1: kt = 4..7 (X=hidden, ih=Wh -> ahi); last iter fills nothing.
    #pragma unroll 2
    for (int kt = 4; kt < 7; kt++) {
        const uint32_t stg  = (kt & 1) ? stage1 : stage0;
        const uint32_t fstg = (kt & 1) ? stage0 : stage1;
        CP_WAIT0();
        __syncthreads();
        compute_tile<true, true>(stg, fstg, aoff0, boff0, fA0, fB0,
                                 pA0, pB, alo, ahi);
    }
    {
        CP_WAIT0();
        __syncthreads();
        compute_tile<true, false>(stage1, stage0, aoff0, boff0, fA0, fB0,
                                  pA0, pB, alo, ahi);
    }

    // ---- register-resident epilogue (biases from global, fp32 hidden) ----
    #pragma unroll
    for (int mi = 0; mi < 2; mi++) {
        #pragma unroll
        for (int unb = 0; unb < 2; unb++) {
            const int ug = n0 + wn * 16 + unb * 8 + 2 * (lane & 3);  // global unit
            const float br0 = __ldg(&bg[ug]),        br1 = __ldg(&bg[ug + 1]);
            const float bz0 = __ldg(&bg[512 + ug]),  bz1 = __ldg(&bg[512 + ug + 1]);
            const float bi0 = __ldg(&bi[ug]),        bi1 = __ldg(&bi[ug + 1]);
            const float bh0 = __ldg(&bh[ug]),        bh1 = __ldg(&bh[ug + 1]);
            #pragma unroll
            for (int half = 0; half < 2; half++) {
                const int m = wm * 32 + mi * 16 + (lane >> 2) + 8 * half;
                const float rv0 = fsigmoid(alo[mi][0 + unb][2 * half]     + br0);
                const float rv1 = fsigmoid(alo[mi][0 + unb][2 * half + 1] + br1);
                const float zv0 = fsigmoid(alo[mi][2 + unb][2 * half]     + bz0);
                const float zv1 = fsigmoid(alo[mi][2 + unb][2 * half + 1] + bz1);
                const float iv0 = alo[mi][4 + unb][2 * half];
                const float iv1 = alo[mi][4 + unb][2 * half + 1];
                const float hv0 = ahi[mi][unb][2 * half];
                const float hv1 = ahi[mi][unb][2 * half + 1];
                const float2 hg = *(const float2*)&hidden[(m0 + m) * 512 + ug];
                const float ng0 = ftanh(iv0 + bi0 + rv0 * (hv0 + bh0));
                const float ng1 = ftanh(iv1 + bi1 + rv1 * (hv1 + bh1));
                float2 o;
                o.x = (1.0f - zv0) * ng0 + zv0 * hg.x;
                o.y = (1.0f - zv1) * ng1 + zv1 * hg.y;
                *(float2*)&out[(m0 + m) * 512 + ug] = o;
            }
        }
    }
}

extern "C" void kernel_launch(void* const* d_in, const int* in_sizes, int n_in,
                              void* d_out, int out_size)
{
    const float* input  = (const float*)d_in[0];
    const float* hidden = (const float*)d_in[1];
    const float* Wg     = (const float*)d_in[2];
    const float* bg     = (const float*)d_in[3];
    const float* Wi     = (const float*)d_in[4];
    const float* bi     = (const float*)d_in[5];
    const float* Wh     = (const float*)d_in[6];
    const float* bh     = (const float*)d_in[7];
    float* out = (float*)d_out;

    // single fused fp32 -> fp16 conversion pass (grid.y segments)
    cvt_all_kernel<<<dim3(CVT_BLOCKS, 3), 256>>>(
        (const float4*)input, (const float4*)hidden,
        (const float4*)Wg, (const float4*)Wi, (const float4*)Wh);

    cudaFuncSetAttribute(gru_mma_kernel,
                         cudaFuncAttributeMaxDynamicSharedMemorySize, SMEM_BYTES);
    // grid.x = 16 n-slices of 32 units, grid.y = 128 batch tiles of 128 rows
    gru_mma_kernel<<<dim3(16, 128), 256, SMEM_BYTES>>>(hidden, bg, bi, bh, out);
}

// round 15
// speedup vs baseline: 1.0254x; 1.0139x over previous
#include <cuda_runtime.h>
#include <cuda_fp16.h>
#include <cstdint>
#include <cstddef>

// ---------------------------------------------------------------------------
// Fused GRU cell, fp16 tensor-core path (compute_103-safe PTX).
// R15: R14 GEMM mainloop (BK=128, 2-stage, 8 barriers, 2 CTAs/SM, fill
// A@ks0 + B@ks1 early-commit) + two overhead cuts:
//   1. cvt processes 2 float4 per thread with a single 16B store.
//   2. the epilogue's fp32 hidden tile is cp.async-prefetched into the dead
//      smem stage during the final compute tile (pitch 144B, conflict-free).
//
// B operand rows (96), per wn slice s = wn*48:
//   rows [s+ 0,s+16): W_gate[n0+wn*16+u]     -> r (nb 0,1)
//   rows [s+16,s+32): W_gate[512+n0+wn*16+u] -> z (nb 2,3)
//   rows [s+32,s+48): Wi/Wh[n0+wn*16+u]      -> i/h (nb 4,5, phase split)
// kt<4: X=input, ih=Wi -> alo. kt>=4: X=hidden, ih=Wh -> ahi.
// ---------------------------------------------------------------------------

// ---- fp16 scratch (device global: allocation-free) ----
static constexpr size_t OFF_IN  = 0;                        // 16384x512
static constexpr size_t OFF_HID = 8388608;                  // 16384x512
static constexpr size_t OFF_WG  = 16777216;                 // 1024x1024
static constexpr size_t OFF_WI  = 17825792;                 // 512x512
static constexpr size_t OFF_WH  = 18087936;                 // 512x512
static constexpr size_t CVT_TOTAL = 18350080;               // 35MB
__device__ __half g_cvt[CVT_TOTAL];

// pair = 2 x float4 = 8 floats -> 8 halfs = one 16B store
static constexpr int NP_X  = 1048576;                       // input/hidden pairs
static constexpr int NP_WG = 131072, NP_WI = 32768, NP_WH = 32768;
static constexpr int NP_W_TOTAL = NP_WG + NP_WI + NP_WH;    // 196608
static constexpr int CVT_BLOCKS = NP_X / 256;               // 4096 (exact)

// grid.y: 0 = input, 1 = hidden, 2 = weights (fused; excess blocks exit)
__global__ void cvt_all_kernel(const float4* __restrict__ input,
                               const float4* __restrict__ hidden,
                               const float4* __restrict__ Wg,
                               const float4* __restrict__ Wi,
                               const float4* __restrict__ Wh) {
    const int i = blockIdx.x * blockDim.x + threadIdx.x;   // pair index
    const int seg = blockIdx.y;
    const float4* src;
    size_t dst_off;
    int j = i;
    if (seg == 0) {
        src = input;  dst_off = OFF_IN;
    } else if (seg == 1) {
        src = hidden; dst_off = OFF_HID;
    } else {
        if (j >= NP_W_TOTAL) return;
        if (j < NP_WG)                 { src = Wg; dst_off = OFF_WG; }
        else if ((j -= NP_WG) < NP_WI) { src = Wi; dst_off = OFF_WI; }
        else { j -= NP_WI;               src = Wh; dst_off = OFF_WH; }
    }
    const float4 v0 = src[2 * j];
    const float4 v1 = src[2 * j + 1];
    __half2 h0 = __floats2half2_rn(v0.x, v0.y);
    __half2 h1 = __floats2half2_rn(v0.z, v0.w);
    __half2 h2 = __floats2half2_rn(v1.x, v1.y);
    __half2 h3 = __floats2half2_rn(v1.z, v1.w);
    uint4 o;
    o.x = *reinterpret_cast<uint32_t*>(&h0);
    o.y = *reinterpret_cast<uint32_t*>(&h1);
    o.z = *reinterpret_cast<uint32_t*>(&h2);
    o.w = *reinterpret_cast<uint32_t*>(&h3);
    reinterpret_cast<uint4*>(g_cvt + dst_off)[j] = o;
}

// ---- helpers ----
__device__ __forceinline__ uint32_t smem_u32(const void* p) {
    uint32_t a;
    asm("{ .reg .u64 t; cvta.to.shared.u64 t, %1; cvt.u32.u64 %0, t; }"
        : "=r"(a) : "l"(p));
    return a;
}

__device__ __forceinline__ void cp16(uint32_t dst, const void* src) {
    asm volatile("cp.async.cg.shared.global [%0], [%1], 16;"
                 :: "r"(dst), "l"(src) : "memory");
}
#define CP_COMMIT() asm volatile("cp.async.commit_group;" ::: "memory")
#define CP_WAIT0()  asm volatile("cp.async.wait_group 0;" ::: "memory")

__device__ __forceinline__ void ldsm4(uint32_t& r0, uint32_t& r1,
                                      uint32_t& r2, uint32_t& r3, uint32_t addr) {
    asm volatile("ldmatrix.sync.aligned.m8n8.x4.shared.b16 {%0,%1,%2,%3}, [%4];"
                 : "=r"(r0), "=r"(r1), "=r"(r2), "=r"(r3) : "r"(addr));
}

__device__ __forceinline__ void mma16(float* c, const uint32_t* a,
                                      uint32_t b0, uint32_t b1) {
    asm volatile(
        "mma.sync.aligned.m16n8k16.row.col.f32.f16.f16.f32 "
        "{%0,%1,%2,%3}, {%4,%5,%6,%7}, {%8,%9}, {%0,%1,%2,%3};"
        : "+f"(c[0]), "+f"(c[1]), "+f"(c[2]), "+f"(c[3])
        : "r"(a[0]), "r"(a[1]), "r"(a[2]), "r"(a[3]), "r"(b0), "r"(b1));
}

__device__ __forceinline__ float fsigmoid(float x) {
    return 1.0f / (1.0f + __expf(-x));
}
__device__ __forceinline__ float ftanh(float x) {
    float e = __expf(2.0f * x);          // overflow->inf, underflow->0: safe
    return 1.0f - 2.0f / (e + 1.0f);
}

// ---- geometry ----
// Rows are 256B (128 fp16). Physical offset of (row, col byte c):
//   row*256 + (c>>7)*128 + ((c&127) ^ ((row&7)<<4))   [SW128 per 128B half]
static constexpr int A_BYTES     = 128 * 256;          // 32KB
static constexpr int B_BYTES     = 96 * 256;           // 24KB
static constexpr int STAGE_BYTES = A_BYTES + B_BYTES;  // 57344
static constexpr int SMEM_BYTES  = 128 + 2 * STAGE_BYTES;  // 114816/CTA
static constexpr int HID_PITCH   = 144;                // fp32 hidden staging pitch

__device__ __forceinline__ uint32_t fill_off(int u) {
    const int r = u >> 4, cu = u & 15;
    return (uint32_t)(r * 256 + ((cu >> 3) << 7) + (((cu & 7) * 16) ^ ((r & 7) << 4)));
}

// Compute one BK=128 tile (8 x k16); optionally interleave next-stage fill.
// Fill schedule (measured best): A's 8 chunks at ks0, B's 6 chunks at ks1,
// COMMIT at ks1 — early LSU issue, ~6.5 ks completion window.
template <bool PH, bool FILL>
__device__ __forceinline__ void compute_tile(
    uint32_t stg, uint32_t fstg, uint32_t aoff0, uint32_t boff0,
    uint32_t fA0, uint32_t fB0,
    const __half*& pA0, const __half* (&pB)[6],
    float (&alo)[2][6][4], float (&ahi)[2][2][4])
{
    uint32_t a[2][2][4];   // A double buffer [buf][mi][reg]
    uint32_t b[6][2];      // B single buffer

    #pragma unroll
    for (int mi = 0; mi < 2; mi++)
        ldsm4(a[0][mi][0], a[0][mi][1], a[0][mi][2], a[0][mi][3],
              stg + aoff0 + mi * 4096);
    #pragma unroll
    for (int p = 0; p < 3; p++)
        ldsm4(b[2 * p][0], b[2 * p][1], b[2 * p + 1][0], b[2 * p + 1][1],
              stg + boff0 + p * 4096);

    #pragma unroll
    for (int ks = 0; ks < 8; ks++) {
        const int cur = ks & 1, nxt = cur ^ 1;
        if (ks < 7) {
            const uint32_t kx = (uint32_t)((ks + 1) << 5);
            #pragma unroll
            for (int mi = 0; mi < 2; mi++)
                ldsm4(a[nxt][mi][0], a[nxt][mi][1], a[nxt][mi][2], a[nxt][mi][3],
                      stg + (aoff0 ^ kx) + mi * 4096);
        }
        if (FILL) {
            if (ks == 0) {             // A: all 8 chunks
                #pragma unroll
                for (int j = 0; j < 8; j++)
                    cp16(fstg + fA0 + (uint32_t)j * 4096u, pA0 + j * 8192);
            } else if (ks == 1) {      // B: all 6 chunks + early commit
                #pragma unroll
                for (int i = 0; i < 6; i++)
                    cp16(fstg + fB0 + (uint32_t)i * 4096u, pB[i]);
                CP_COMMIT();
            }
        }
        #pragma unroll
        for (int mi = 0; mi < 2; mi++) {
            #pragma unroll
            for (int nb = 0; nb < 6; nb++) {
                if (PH && nb >= 4)
                    mma16(ahi[mi][nb - 4], a[cur][mi], b[nb][0], b[nb][1]);
                else
                    mma16(alo[mi][nb], a[cur][mi], b[nb][0], b[nb][1]);
            }
        }
        if (ks < 7) {
            const uint32_t kx = (uint32_t)((ks + 1) << 5);
            #pragma unroll
            for (int p = 0; p < 3; p++)
                ldsm4(b[2 * p][0], b[2 * p][1], b[2 * p + 1][0], b[2 * p + 1][1],
                      stg + (boff0 ^ kx) + p * 4096);
        }
    }
    if (FILL) {
        pA0 += 128;
        #pragma unroll
        for (int i = 0; i < 6; i++) pB[i] += 128;
    }
}

__global__ void __launch_bounds__(256, 2)
gru_mma_kernel(const float* __restrict__ hidden,
               const float* __restrict__ bg, const float* __restrict__ bi,
               const float* __restrict__ bh, float* __restrict__ out)
{
    extern __shared__ char dsm[];
    const int tid  = threadIdx.x;
    const int lane = tid & 31;
    const int wid  = tid >> 5;
    const int wm   = wid >> 1;          // 0..3 (M, 32 rows each)
    const int wn   = wid & 1;           // 0..1 (N slice, 16 units each)
    const int n0 = blockIdx.x * 32;     // hidden-unit slice
    const int m0 = blockIdx.y * 128;    // batch-row slice

    const __half* cIn  = g_cvt + OFF_IN;
    const __half* cHid = g_cvt + OFF_HID;
    const __half* cWg  = g_cvt + OFF_WG;
    const __half* cWi  = g_cvt + OFF_WI;
    const __half* cWh  = g_cvt + OFF_WH;

    const uint32_t raw = smem_u32(dsm);
    const uint32_t sb  = (raw + 127u) & ~127u;
    const uint32_t stage0 = sb;
    const uint32_t stage1 = stage0 + STAGE_BYTES;
    char* gb = dsm + (sb - raw);        // C++ pointer mirror of sb

    // ---- fill state (16B chunk = 8 halfs; 16 chunks per 256B row) ----
    const uint32_t fA0 = fill_off(tid);                        // + j*4096
    const uint32_t fB0 = (uint32_t)A_BYTES + fill_off(tid);    // + i*4096
    const int frow = tid >> 4, fcu = (tid & 15) * 8;
    const __half* pA0 = cIn + (m0 + frow) * 512 + fcu;         // + j*8192 halfs
    const __half* pB[6];
    bool isw[6];
    #pragma unroll
    for (int i = 0; i < 6; i++) {
        const int r = frow + 16 * i;        // 0..95
        const int ws = (r >= 48) ? 1 : 0, rr = r - ws * 48;
        const int un = n0 + ws * 16;
        isw[i] = (rr >= 32);
        if (rr < 16)       pB[i] = cWg + (un + rr) * 1024 + fcu;
        else if (rr < 32)  pB[i] = cWg + (512 + un + rr - 16) * 1024 + fcu;
        else               pB[i] = cWi + (un + rr - 32) * 512 + fcu;
    }
    // Phase switch (after 4 fills of +128): xa = in+row*512+512 -> hid+row*512.
    const ptrdiff_t dxa = (cHid - cIn) - 512;
    const ptrdiff_t dwh = (cWh - cWi) - 512;

    // ---- LDSM base offsets ----
    uint32_t aoff0, boff0;
    {
        const uint32_t arow = (uint32_t)(wm * 32 + (lane & 7) + ((lane >> 3) & 1) * 8);
        const uint32_t acb  = (uint32_t)((lane >> 4) * 16);
        const uint32_t brow = (uint32_t)(wn * 48 + ((lane >> 4) * 8) + (lane & 7));
        const uint32_t bcb  = (uint32_t)(((lane >> 3) & 1) * 16);
        aoff0 = arow * 256 + (acb ^ ((arow & 7) << 4));                     // + mi*4096
        boff0 = (uint32_t)A_BYTES + brow * 256 + (bcb ^ ((brow & 7) << 4)); // + p*4096
    }

    float alo[2][6][4];
    float ahi[2][2][4];
    #pragma unroll
    for (int mi = 0; mi < 2; mi++) {
        #pragma unroll
        for (int nb = 0; nb < 6; nb++)
            #pragma unroll
            for (int e = 0; e < 4; e++) alo[mi][nb][e] = 0.0f;
        #pragma unroll
        for (int nb = 0; nb < 2; nb++)
            #pragma unroll
            for (int e = 0; e < 4; e++) ahi[mi][nb][e] = 0.0f;
    }

    // prologue: fill stage0 for kt=0
    {
        #pragma unroll
        for (int j = 0; j < 8; j++)
            cp16(stage0 + fA0 + (uint32_t)j * 4096u, pA0 + j * 8192);
        pA0 += 128;
        #pragma unroll
        for (int i = 0; i < 6; i++) {
            cp16(stage0 + fB0 + (uint32_t)i * 4096u, pB[i]);
            pB[i] += 128;
        }
        CP_COMMIT();
    }

    // Phase 0: kt = 0..3 (X=input, ih=Wi -> alo)
    #pragma unroll 2
    for (int kt = 0; kt < 4; kt++) {
        const uint32_t stg  = (kt & 1) ? stage1 : stage0;
        const uint32_t fstg = (kt & 1) ? stage0 : stage1;
        CP_WAIT0();
        __syncthreads();
        if (kt == 3) {   // next fill f=4: switch xa->hidden, Wi->Wh
            pA0 += dxa;
            #pragma unroll
            for (int i = 0; i < 6; i++) if (isw[i]) pB[i] += dwh;
        }
        compute_tile<false, true>(stg, fstg, aoff0, boff0, fA0, fB0,
                                  pA0, pB, alo, ahi);
    }
    // Phase 1: kt = 4..6 fill; kt=7 computes stage1 while stage0 receives the
    // fp32 hidden tile for the epilogue.
    #pragma unroll 2
    for (int kt = 4; kt < 7; kt++) {
        const uint32_t stg  = (kt & 1) ? stage1 : stage0;
        const uint32_t fstg = (kt & 1) ? stage0 : stage1;
        CP_WAIT0();
        __syncthreads();
        compute_tile<true, true>(stg, fstg, aoff0, boff0, fA0, fB0,
                                 pA0, pB, alo, ahi);
    }
    {
        CP_WAIT0();
        __syncthreads();
        // Prefetch fp32 hidden tile (128 rows x 32 floats, pitch 144B) into
        // the dead stage0; latency hides under the final tile's MMAs.
        #pragma unroll
        for (int i = 0; i < 4; i++) {
            const int u = tid + i * 256, r = u >> 3, c = u & 7;
            cp16(stage0 + (uint32_t)(r * HID_PITCH + c * 16),
                 hidden + (m0 + r) * 512 + n0 + c * 4);
        }
        CP_COMMIT();
        compute_tile<true, false>(stage1, stage0, aoff0, boff0, fA0, fB0,
                                  pA0, pB, alo, ahi);
        CP_WAIT0();
        __syncthreads();
    }

    // ---- register-resident epilogue (biases from global, hidden from smem) ----
    const char* s_hid = gb;   // stage0: fp32 hidden tile, pitch HID_PITCH
    #pragma unroll
    for (int mi = 0; mi < 2; mi++) {
        #pragma unroll
        for (int unb = 0; unb < 2; unb++) {
            const int uu = wn * 16 + unb * 8 + 2 * (lane & 3);   // local unit
            const int ug = n0 + uu;                              // global unit
            const float br0 = __ldg(&bg[ug]),        br1 = __ldg(&bg[ug + 1]);
            const float bz0 = __ldg(&bg[512 + ug]),  bz1 = __ldg(&bg[512 + ug + 1]);
            const float bi0 = __ldg(&bi[ug]),        bi1 = __ldg(&bi[ug + 1]);
            const float bh0 = __ldg(&bh[ug]),        bh1 = __ldg(&bh[ug + 1]);
            #pragma unroll
            for (int half = 0; half < 2; half++) {
                const int m = wm * 32 + mi * 16 + (lane >> 2) + 8 * half;
                const float rv0 = fsigmoid(alo[mi][0 + unb][2 * half]     + br0);
                const float rv1 = fsigmoid(alo[mi][0 + unb][2 * half + 1] + br1);
                const float zv0 = fsigmoid(alo[mi][2 + unb][2 * half]     + bz0);
                const float zv1 = fsigmoid(alo[mi][2 + unb][2 * half + 1] + bz1);
                const float iv0 = alo[mi][4 + unb][2 * half];
                const float iv1 = alo[mi][4 + unb][2 * half + 1];
                const float hv0 = ahi[mi][unb][2 * half];
                const float hv1 = ahi[mi][unb][2 * half + 1];
                const float2 hg = *(const float2*)(s_hid + m * HID_PITCH + uu * 4);
                const float ng0 = ftanh(iv0 + bi0 + rv0 * (hv0 + bh0));
                const float ng1 = ftanh(iv1 + bi1 + rv1 * (hv1 + bh1));
                float2 o;
                o.x = (1.0f - zv0) * ng0 + zv0 * hg.x;
                o.y = (1.0f - zv1) * ng1 + zv1 * hg.y;
                *(float2*)&out[(m0 + m) * 512 + ug] = o;
            }
        }
    }
}

extern "C" void kernel_launch(void* const* d_in, const int* in_sizes, int n_in,
                              void* d_out, int out_size)
{
    const float* input  = (const float*)d_in[0];
    const float* hidden = (const float*)d_in[1];
    const float* Wg     = (const float*)d_in[2];
    const float* bg     = (const float*)d_in[3];
    const float* Wi     = (const float*)d_in[4];
    const float* bi     = (const float*)d_in[5];
    const float* Wh     = (const float*)d_in[6];
    const float* bh     = (const float*)d_in[7];
    float* out = (float*)d_out;

    // single fused fp32 -> fp16 conversion pass (2 float4/thread, 16B stores)
    cvt_all_kernel<<<dim3(CVT_BLOCKS, 3), 256>>>(
        (const float4*)input, (const float4*)hidden,
        (const float4*)Wg, (const float4*)Wi, (const float4*)Wh);

    cudaFuncSetAttribute(gru_mma_kernel,
                         cudaFuncAttributeMaxDynamicSharedMemorySize, SMEM_BYTES);
    // grid.x = 16 n-slices of 32 units, grid.y = 128 batch tiles of 128 rows
    gru_mma_kernel<<<dim3(16, 128), 256, SMEM_BYTES>>>(hidden, bg, bi, bh, out);
}

// round 16
// speedup vs baseline: 1.0443x; 1.0184x over previous
#include <cuda_runtime.h>
#include <cuda_fp16.h>
#include <cstdint>
#include <cstddef>

// ---------------------------------------------------------------------------
// Fused GRU cell, fp16 tensor-core path (compute_103-safe PTX).
// R16: final recombination of measured-best components —
//   GEMM  = R14 verbatim (132.4us measured): BK=128, 2-stage, 8 barriers,
//           2 CTAs/SM, fill A@ks0 + B@ks1 early-commit, epilogue with
//           __ldg biases and direct global fp32 hidden (no tail prefetch).
//   cvt   = R15 (16us measured): single launch, 2 float4/thread, 16B stores.
//
// B operand rows (96), per wn slice s = wn*48:
//   rows [s+ 0,s+16): W_gate[n0+wn*16+u]     -> r (nb 0,1)
//   rows [s+16,s+32): W_gate[512+n0+wn*16+u] -> z (nb 2,3)
//   rows [s+32,s+48): Wi/Wh[n0+wn*16+u]      -> i/h (nb 4,5, phase split)
// kt<4: X=input, ih=Wi -> alo. kt>=4: X=hidden, ih=Wh -> ahi.
// Epilogue uses ORIGINAL fp32 hidden for the z*h term.
// ---------------------------------------------------------------------------

// ---- fp16 scratch (device global: allocation-free) ----
static constexpr size_t OFF_IN  = 0;                        // 16384x512
static constexpr size_t OFF_HID = 8388608;                  // 16384x512
static constexpr size_t OFF_WG  = 16777216;                 // 1024x1024
static constexpr size_t OFF_WI  = 17825792;                 // 512x512
static constexpr size_t OFF_WH  = 18087936;                 // 512x512
static constexpr size_t CVT_TOTAL = 18350080;               // 35MB
__device__ __half g_cvt[CVT_TOTAL];

// pair = 2 x float4 = 8 floats -> 8 halfs = one 16B store
static constexpr int NP_X  = 1048576;                       // input/hidden pairs
static constexpr int NP_WG = 131072, NP_WI = 32768, NP_WH = 32768;
static constexpr int NP_W_TOTAL = NP_WG + NP_WI + NP_WH;    // 196608
static constexpr int CVT_BLOCKS = NP_X / 256;               // 4096 (exact)

// grid.y: 0 = input, 1 = hidden, 2 = weights (fused; excess blocks exit)
__global__ void cvt_all_kernel(const float4* __restrict__ input,
                               const float4* __restrict__ hidden,
                               const float4* __restrict__ Wg,
                               const float4* __restrict__ Wi,
                               const float4* __restrict__ Wh) {
    const int i = blockIdx.x * blockDim.x + threadIdx.x;   // pair index
    const int seg = blockIdx.y;
    const float4* src;
    size_t dst_off;
    int j = i;
    if (seg == 0) {
        src = input;  dst_off = OFF_IN;
    } else if (seg == 1) {
        src = hidden; dst_off = OFF_HID;
    } else {
        if (j >= NP_W_TOTAL) return;
        if (j < NP_WG)                 { src = Wg; dst_off = OFF_WG; }
        else if ((j -= NP_WG) < NP_WI) { src = Wi; dst_off = OFF_WI; }
        else { j -= NP_WI;               src = Wh; dst_off = OFF_WH; }
    }
    const float4 v0 = src[2 * j];
    const float4 v1 = src[2 * j + 1];
    __half2 h0 = __floats2half2_rn(v0.x, v0.y);
    __half2 h1 = __floats2half2_rn(v0.z, v0.w);
    __half2 h2 = __floats2half2_rn(v1.x, v1.y);
    __half2 h3 = __floats2half2_rn(v1.z, v1.w);
    uint4 o;
    o.x = *reinterpret_cast<uint32_t*>(&h0);
    o.y = *reinterpret_cast<uint32_t*>(&h1);
    o.z = *reinterpret_cast<uint32_t*>(&h2);
    o.w = *reinterpret_cast<uint32_t*>(&h3);
    reinterpret_cast<uint4*>(g_cvt + dst_off)[j] = o;
}

// ---- helpers ----
__device__ __forceinline__ uint32_t smem_u32(const void* p) {
    uint32_t a;
    asm("{ .reg .u64 t; cvta.to.shared.u64 t, %1; cvt.u32.u64 %0, t; }"
        : "=r"(a) : "l"(p));
    return a;
}

__device__ __forceinline__ void cp16(uint32_t dst, const void* src) {
    asm volatile("cp.async.cg.shared.global [%0], [%1], 16;"
                 :: "r"(dst), "l"(src) : "memory");
}
#define CP_COMMIT() asm volatile("cp.async.commit_group;" ::: "memory")
#define CP_WAIT0()  asm volatile("cp.async.wait_group 0;" ::: "memory")

__device__ __forceinline__ void ldsm4(uint32_t& r0, uint32_t& r1,
                                      uint32_t& r2, uint32_t& r3, uint32_t addr) {
    asm volatile("ldmatrix.sync.aligned.m8n8.x4.shared.b16 {%0,%1,%2,%3}, [%4];"
                 : "=r"(r0), "=r"(r1), "=r"(r2), "=r"(r3) : "r"(addr));
}

__device__ __forceinline__ void mma16(float* c, const uint32_t* a,
                                      uint32_t b0, uint32_t b1) {
    asm volatile(
        "mma.sync.aligned.m16n8k16.row.col.f32.f16.f16.f32 "
        "{%0,%1,%2,%3}, {%4,%5,%6,%7}, {%8,%9}, {%0,%1,%2,%3};"
        : "+f"(c[0]), "+f"(c[1]), "+f"(c[2]), "+f"(c[3])
        : "r"(a[0]), "r"(a[1]), "r"(a[2]), "r"(a[3]), "r"(b0), "r"(b1));
}

__device__ __forceinline__ float fsigmoid(float x) {
    return 1.0f / (1.0f + __expf(-x));
}
__device__ __forceinline__ float ftanh(float x) {
    float e = __expf(2.0f * x);          // overflow->inf, underflow->0: safe
    return 1.0f - 2.0f / (e + 1.0f);
}

// ---- geometry ----
// Rows are 256B (128 fp16). Physical offset of (row, col byte c):
//   row*256 + (c>>7)*128 + ((c&127) ^ ((row&7)<<4))   [SW128 per 128B half]
static constexpr int A_BYTES     = 128 * 256;          // 32KB
static constexpr int B_BYTES     = 96 * 256;           // 24KB
static constexpr int STAGE_BYTES = A_BYTES + B_BYTES;  // 57344
static constexpr int SMEM_BYTES  = 128 + 2 * STAGE_BYTES;  // 114816/CTA

__device__ __forceinline__ uint32_t fill_off(int u) {
    const int r = u >> 4, cu = u & 15;
    return (uint32_t)(r * 256 + ((cu >> 3) << 7) + (((cu & 7) * 16) ^ ((r & 7) << 4)));
}

// Compute one BK=128 tile (8 x k16); optionally interleave next-stage fill.
// Fill schedule (measured best): A's 8 chunks at ks0, B's 6 chunks at ks1,
// COMMIT at ks1 — early LSU issue, ~6.5 ks completion window.
template <bool PH, bool FILL>
__device__ __forceinline__ void compute_tile(
    uint32_t stg, uint32_t fstg, uint32_t aoff0, uint32_t boff0,
    uint32_t fA0, uint32_t fB0,
    const __half*& pA0, const __half* (&pB)[6],
    float (&alo)[2][6][4], float (&ahi)[2][2][4])
{
    uint32_t a[2][2][4];   // A double buffer [buf][mi][reg]
    uint32_t b[6][2];      // B single buffer

    #pragma unroll
    for (int mi = 0; mi < 2; mi++)
        ldsm4(a[0][mi][0], a[0][mi][1], a[0][mi][2], a[0][mi][3],
              stg + aoff0 + mi * 4096);
    #pragma unroll
    for (int p = 0; p < 3; p++)
        ldsm4(b[2 * p][0], b[2 * p][1], b[2 * p + 1][0], b[2 * p + 1][1],
              stg + boff0 + p * 4096);

    #pragma unroll
    for (int ks = 0; ks < 8; ks++) {
        const int cur = ks & 1, nxt = cur ^ 1;
        if (ks < 7) {
            const uint32_t kx = (uint32_t)((ks + 1) << 5);
            #pragma unroll
            for (int mi = 0; mi < 2; mi++)
                ldsm4(a[nxt][mi][0], a[nxt][mi][1], a[nxt][mi][2], a[nxt][mi][3],
                      stg + (aoff0 ^ kx) + mi * 4096);
        }
        if (FILL) {
            if (ks == 0) {             // A: all 8 chunks
                #pragma unroll
                for (int j = 0; j < 8; j++)
                    cp16(fstg + fA0 + (uint32_t)j * 4096u, pA0 + j * 8192);
            } else if (ks == 1) {      // B: all 6 chunks + early commit
                #pragma unroll
                for (int i = 0; i < 6; i++)
                    cp16(fstg + fB0 + (uint32_t)i * 4096u, pB[i]);
                CP_COMMIT();
            }
        }
        #pragma unroll
        for (int mi = 0; mi < 2; mi++) {
            #pragma unroll
            for (int nb = 0; nb < 6; nb++) {
                if (PH && nb >= 4)
                    mma16(ahi[mi][nb - 4], a[cur][mi], b[nb][0], b[nb][1]);
                else
                    mma16(alo[mi][nb], a[cur][mi], b[nb][0], b[nb][1]);
            }
        }
        if (ks < 7) {
            const uint32_t kx = (uint32_t)((ks + 1) << 5);
            #pragma unroll
            for (int p = 0; p < 3; p++)
                ldsm4(b[2 * p][0], b[2 * p][1], b[2 * p + 1][0], b[2 * p + 1][1],
                      stg + (boff0 ^ kx) + p * 4096);
        }
    }
    if (FILL) {
        pA0 += 128;
        #pragma unroll
        for (int i = 0; i < 6; i++) pB[i] += 128;
    }
}

__global__ void __launch_bounds__(256, 2)
gru_mma_kernel(const float* __restrict__ hidden,
               const float* __restrict__ bg, const float* __restrict__ bi,
               const float* __restrict__ bh, float* __restrict__ out)
{
    extern __shared__ char dsm[];
    const int tid  = threadIdx.x;
    const int lane = tid & 31;
    const int wid  = tid >> 5;
    const int wm   = wid >> 1;          // 0..3 (M, 32 rows each)
    const int wn   = wid & 1;           // 0..1 (N slice, 16 units each)
    const int n0 = blockIdx.x * 32;     // hidden-unit slice
    const int m0 = blockIdx.y * 128;    // batch-row slice

    const __half* cIn  = g_cvt + OFF_IN;
    const __half* cHid = g_cvt + OFF_HID;
    const __half* cWg  = g_cvt + OFF_WG;
    const __half* cWi  = g_cvt + OFF_WI;
    const __half* cWh  = g_cvt + OFF_WH;

    const uint32_t raw = smem_u32(dsm);
    const uint32_t sb  = (raw + 127u) & ~127u;
    const uint32_t stage0 = sb;
    const uint32_t stage1 = stage0 + STAGE_BYTES;

    // ---- fill state (16B chunk = 8 halfs; 16 chunks per 256B row) ----
    const uint32_t fA0 = fill_off(tid);                        // + j*4096
    const uint32_t fB0 = (uint32_t)A_BYTES + fill_off(tid);    // + i*4096
    const int frow = tid >> 4, fcu = (tid & 15) * 8;
    const __half* pA0 = cIn + (m0 + frow) * 512 + fcu;         // + j*8192 halfs
    const __half* pB[6];
    bool isw[6];
    #pragma unroll
    for (int i = 0; i < 6; i++) {
        const int r = frow + 16 * i;        // 0..95
        const int ws = (r >= 48) ? 1 : 0, rr = r - ws * 48;
        const int un = n0 + ws * 16;
        isw[i] = (rr >= 32);
        if (rr < 16)       pB[i] = cWg + (un + rr) * 1024 + fcu;
        else if (rr < 32)  pB[i] = cWg + (512 + un + rr - 16) * 1024 + fcu;
        else               pB[i] = cWi + (un + rr - 32) * 512 + fcu;
    }
    // Phase switch (after 4 fills of +128): xa = in+row*512+512 -> hid+row*512.
    const ptrdiff_t dxa = (cHid - cIn) - 512;
    const ptrdiff_t dwh = (cWh - cWi) - 512;

    // ---- LDSM base offsets ----
    uint32_t aoff0, boff0;
    {
        const uint32_t arow = (uint32_t)(wm * 32 + (lane & 7) + ((lane >> 3) & 1) * 8);
        const uint32_t acb  = (uint32_t)((lane >> 4) * 16);
        const uint32_t brow = (uint32_t)(wn * 48 + ((lane >> 4) * 8) + (lane & 7));
        const uint32_t bcb  = (uint32_t)(((lane >> 3) & 1) * 16);
        aoff0 = arow * 256 + (acb ^ ((arow & 7) << 4));                     // + mi*4096
        boff0 = (uint32_t)A_BYTES + brow * 256 + (bcb ^ ((brow & 7) << 4)); // + p*4096
    }

    float alo[2][6][4];
    float ahi[2][2][4];
    #pragma unroll
    for (int mi = 0; mi < 2; mi++) {
        #pragma unroll
        for (int nb = 0; nb < 6; nb++)
            #pragma unroll
            for (int e = 0; e < 4; e++) alo[mi][nb][e] = 0.0f;
        #pragma unroll
        for (int nb = 0; nb < 2; nb++)
            #pragma unroll
            for (int e = 0; e < 4; e++) ahi[mi][nb][e] = 0.0f;
    }

    // prologue: fill stage0 for kt=0
    {
        #pragma unroll
        for (int j = 0; j < 8; j++)
            cp16(stage0 + fA0 + (uint32_t)j * 4096u, pA0 + j * 8192);
        pA0 += 128;
        #pragma unroll
        for (int i = 0; i < 6; i++) {
            cp16(stage0 + fB0 + (uint32_t)i * 4096u, pB[i]);
            pB[i] += 128;
        }
        CP_COMMIT();
    }

    // Phase 0: kt = 0..3 (X=input, ih=Wi -> alo)
    #pragma unroll 2
    for (int kt = 0; kt < 4; kt++) {
        const uint32_t stg  = (kt & 1) ? stage1 : stage0;
        const uint32_t fstg = (kt & 1) ? stage0 : stage1;
        CP_WAIT0();
        __syncthreads();
        if (kt == 3) {   // next fill f=4: switch xa->hidden, Wi->Wh
            pA0 += dxa;
            #pragma unroll
            for (int i = 0; i < 6; i++) if (isw[i]) pB[i] += dwh;
        }
        compute_tile<false, true>(stg, fstg, aoff0, boff0, fA0, fB0,
                                  pA0, pB, alo, ahi);
    }
    // Phase 1: kt = 4..7 (X=hidden, ih=Wh -> ahi); last iter fills nothing.
    #pragma unroll 2
    for (int kt = 4; kt < 7; kt++) {
        const uint32_t stg  = (kt & 1) ? stage1 : stage0;
        const uint32_t fstg = (kt & 1) ? stage0 : stage1;
        CP_WAIT0();
        __syncthreads();
        compute_tile<true, true>(stg, fstg, aoff0, boff0, fA0, fB0,
                                 pA0, pB, alo, ahi);
    }
    {
        CP_WAIT0();
        __syncthreads();
        compute_tile<true, false>(stage1, stage0, aoff0, boff0, fA0, fB0,
                                  pA0, pB, alo, ahi);
    }

    // ---- register-resident epilogue (biases from global, fp32 hidden) ----
    #pragma unroll
    for (int mi = 0; mi < 2; mi++) {
        #pragma unroll
        for (int unb = 0; unb < 2; unb++) {
            const int ug = n0 + wn * 16 + unb * 8 + 2 * (lane & 3);  // global unit
            const float br0 = __ldg(&bg[ug]),        br1 = __ldg(&bg[ug + 1]);
            const float bz0 = __ldg(&bg[512 + ug]),  bz1 = __ldg(&bg[512 + ug + 1]);
            const float bi0 = __ldg(&bi[ug]),        bi1 = __ldg(&bi[ug + 1]);
            const float bh0 = __ldg(&bh[ug]),        bh1 = __ldg(&bh[ug + 1]);
            #pragma unroll
            for (int half = 0; half < 2; half++) {
                const int m = wm * 32 + mi * 16 + (lane >> 2) + 8 * half;
                const float rv0 = fsigmoid(alo[mi][0 + unb][2 * half]     + br0);
                const float rv1 = fsigmoid(alo[mi][0 + unb][2 * half + 1] + br1);
                const float zv0 = fsigmoid(alo[mi][2 + unb][2 * half]     + bz0);
                const float zv1 = fsigmoid(alo[mi][2 + unb][2 * half + 1] + bz1);
                const float iv0 = alo[mi][4 + unb][2 * half];
                const float iv1 = alo[mi][4 + unb][2 * half + 1];
                const float hv0 = ahi[mi][unb][2 * half];
                const float hv1 = ahi[mi][unb][2 * half + 1];
                const float2 hg = *(const float2*)&hidden[(m0 + m) * 512 + ug];
                const float ng0 = ftanh(iv0 + bi0 + rv0 * (hv0 + bh0));
                const float ng1 = ftanh(iv1 + bi1 + rv1 * (hv1 + bh1));
                float2 o;
                o.x = (1.0f - zv0) * ng0 + zv0 * hg.x;
                o.y = (1.0f - zv1) * ng1 + zv1 * hg.y;
                *(float2*)&out[(m0 + m) * 512 + ug] = o;
            }
        }
    }
}

extern "C" void kernel_launch(void* const* d_in, const int* in_sizes, int n_in,
                              void* d_out, int out_size)
{
    const float* input  = (const float*)d_in[0];
    const float* hidden = (const float*)d_in[1];
    const float* Wg     = (const float*)d_in[2];
    const float* bg     = (const float*)d_in[3];
    const float* Wi     = (const float*)d_in[4];
    const float* bi     = (const float*)d_in[5];
    const float* Wh     = (const float*)d_in[6];
    const float* bh     = (const float*)d_in[7];
    float* out = (float*)d_out;

    // single fused fp32 -> fp16 conversion pass (2 float4/thread, 16B stores)
    cvt_all_kernel<<<dim3(CVT_BLOCKS, 3), 256>>>(
        (const float4*)input, (const float4*)hidden,
        (const float4*)Wg, (const float4*)Wi, (const float4*)Wh);

    cudaFuncSetAttribute(gru_mma_kernel,
                         cudaFuncAttributeMaxDynamicSharedMemorySize, SMEM_BYTES);
    // grid.x = 16 n-slices of 32 units, grid.y = 128 batch tiles of 128 rows
    gru_mma_kernel<<<dim3(16, 128), 256, SMEM_BYTES>>>(hidden, bg, bi, bh, out);
}